// round 13
// baseline (speedup 1.0000x reference)
#include <cuda_runtime.h>

#define NMAX  1536
#define TPB   256
#define EPT   6          // strided elements per thread (NMAX / TPB)
#define NWARP 8
#define NITER 20
#define SORTB 2048

__device__ int g_maxdeg;
__device__ int g_perm[SORTB];

// ---------------------------------------------------------------------------
// Kernel 1 (pre): per-group offset (redundant prefix sum) + degree count
// -> global max degree. Block 0 additionally builds the LPT permutation
// (groups sorted by size descending) into g_perm.
// ---------------------------------------------------------------------------
__global__ void __launch_bounds__(512)
pre_kernel(const int* __restrict__ sizes,
           const int* __restrict__ edges,
           int N, int B) {
    __shared__ int cnt[NMAX];
    __shared__ int red[16];
    __shared__ int s_off;
    __shared__ int skey[SORTB];

    int g = blockIdx.x;
    int t = threadIdx.x;
    int lane = t & 31, wid = t >> 5;

    int part = 0;
    for (int i = t; i < g; i += 512) part += sizes[i];
#pragma unroll
    for (int d = 16; d; d >>= 1) part += __shfl_xor_sync(0xffffffffu, part, d);
    if (lane == 0) red[wid] = part;
    __syncthreads();
    if (t == 0) {
        int s = 0;
#pragma unroll
        for (int w = 0; w < 16; ++w) s += red[w];
        s_off = s;
    }
    int n = sizes[g];
    __syncthreads();
    int off = s_off;

    for (int i = t; i < n; i += 512)
        cnt[i] = (i == 0 || i == n - 1) ? 1 : 2;
    __syncthreads();

    const int2* e2 = (const int2*)edges;
    int reBase = (N - B) + off;
    for (int i = t; i < n; i += 512) {
        int2 e = e2[reBase + i];
        atomicAdd(&cnt[e.x - off], 1);
        atomicAdd(&cnt[e.y - off], 1);
    }
    __syncthreads();

    int m = 0;
    for (int i = t; i < n; i += 512) m = max(m, cnt[i]);
#pragma unroll
    for (int d = 16; d; d >>= 1) m = max(m, __shfl_xor_sync(0xffffffffu, m, d));
    if (lane == 0) red[wid] = m;
    __syncthreads();
    if (t == 0) {
        int mm = red[0];
#pragma unroll
        for (int w = 1; w < 16; ++w) mm = max(mm, red[w]);
        atomicMax(&g_maxdeg, mm);
    }

    // ---- block 0: LPT permutation (descending size) ----
    if (g == 0) {
        for (int i = t; i < SORTB; i += 512)
            skey[i] = (i < B) ? ((sizes[i] << 11) | i) : -1;
        __syncthreads();
        for (int k = 2; k <= SORTB; k <<= 1) {
            for (int jj = k >> 1; jj > 0; jj >>= 1) {
                for (int i = t; i < SORTB; i += 512) {
                    int ix = i ^ jj;
                    if (ix > i) {
                        int a = skey[i], b = skey[ix];
                        bool up = ((i & k) == 0);      // descending network
                        if ((a < b) == up) { skey[i] = b; skey[ix] = a; }
                    }
                }
                __syncthreads();
            }
        }
        for (int i = t; i < SORTB; i += 512)
            g_perm[i] = skey[i] & 2047;
    }
}

// ---------------------------------------------------------------------------
// Kernel 2 (main): fused per-group solve (group = g_perm[blockIdx]).
// Unique-slot stores ev[4*node + slot] for slot<3; slot 3 is a rare-atomic
// overflow accumulator. float4 gather; Michelot sparsemax.
// ---------------------------------------------------------------------------
__global__ void __launch_bounds__(TPB, 3)
main_kernel(const float* __restrict__ x,
            const int*   __restrict__ sizes,
            const int*   __restrict__ edges,
            float*       __restrict__ out,
            int N, int B) {
    __shared__ float ys[NMAX];
    __shared__ float uc[NMAX];          // aliased as int cnt[] during setup
    __shared__ float ev[4 * NMAX];      // slots 0-2 unique, slot 3 overflow accum
    __shared__ float red_s[NWARP];
    __shared__ int   red_c[NWARP];
    __shared__ int   red_i[NWARP];
    __shared__ float s_tau;
    __shared__ int   s_cnt;
    __shared__ int   s_off;

    int g = g_perm[blockIdx.x];
    int t = threadIdx.x;
    int lane = t & 31, wid = t >> 5;

    // offset[g] = sum of sizes[0..g)  (redundant recompute; L2-resident)
    {
        int part = 0;
        for (int i = t; i < g; i += TPB) part += sizes[i];
#pragma unroll
        for (int d = 16; d; d >>= 1) part += __shfl_xor_sync(0xffffffffu, part, d);
        if (lane == 0) red_i[wid] = part;
        __syncthreads();
        if (t == 0) {
            int s = 0;
#pragma unroll
            for (int w = 0; w < NWARP; ++w) s += red_i[w];
            s_off = s;
        }
    }
    int n = sizes[g];
    __syncthreads();
    int off = s_off;
    int reBase = (N - B) + off;

    int* cnt = (int*)uc;

    float xr[EPT], yv[EPT], ucv[EPT], ur[EPT];
    int   ea[EPT], eb[EPT];
    unsigned slp[EPT];     // packed slot addrs: sa | (sb<<16); 0xFFFF = overflow

    // ---- setup ----
#pragma unroll
    for (int j = 0; j < EPT; ++j) cnt[t + j * TPB] = 0;
#pragma unroll
    for (int k = 0; k < 4 * EPT; ++k)
        ev[t + k * TPB] = 0.0f;
    __syncthreads();

    const int2* e2 = (const int2*)edges;
#pragma unroll
    for (int j = 0; j < EPT; ++j) {
        int i = t + j * TPB;
        bool a = (j < 2) || (i < n);   // first 512 slots always active (n>=512)
        if (a) {
            xr[j] = x[off + i];
            int2 e = e2[reBase + i];
            ea[j] = e.x - off;
            eb[j] = e.y - off;
            ys[i] = xr[j];
            int pa = atomicAdd(&cnt[ea[j]], 1);
            int pb = atomicAdd(&cnt[eb[j]], 1);
            unsigned sa = (pa < 3) ? (unsigned)(4 * ea[j] + pa) : 0xFFFFu;
            unsigned sb = (pb < 3) ? (unsigned)(4 * eb[j] + pb) : 0xFFFFu;
            slp[j] = sa | (sb << 16);
        } else {
            xr[j] = 0.0f; ea[j] = 0; eb[j] = 0;
            ys[i] = 0.0f;
            slp[j] = 0xFFFFu | (0xFFFFu << 16);
        }
        yv[j]  = xr[j];
        ur[j]  = 0.0f;
        ucv[j] = 0.0f;
    }
    __syncthreads();
    // overwrite cnt with uc = 0
#pragma unroll
    for (int j = 0; j < EPT; ++j)
        uc[t + j * TPB] = 0.0f;
    float step = 0.5f / (float)g_maxdeg;
    __syncthreads();

    // ---- 20 iterations, 2 barriers each ----
    for (int it = 0; it < NITER; ++it) {
        // Phase P: dual updates from current y; publish contributions.
#pragma unroll
        for (int j = 0; j < EPT; ++j) {
            int i = t + j * TPB;
            bool a = (j < 2) || (i < n);
            if (a) {
                if (i < n - 1) {
                    float nu = ucv[j] + step * (yv[j] - ys[i + 1]);
                    nu = fminf(1.0f, fmaxf(-1.0f, nu));
                    ucv[j] = nu;
                    uc[i] = nu;
                }
                float ya = ys[ea[j]], yb = ys[eb[j]];
                float nu = ur[j] + step * (ya - yb);
                nu = fminf(1.0f, fmaxf(-1.0f, nu));
                unsigned sa = slp[j] & 0xFFFFu;
                unsigned sb = slp[j] >> 16;
                if (sa != 0xFFFFu) ev[sa] = -nu;
                else               atomicAdd(&ev[4 * ea[j] + 3], -(nu - ur[j]));
                if (sb != 0xFFFFu) ev[sb] =  nu;
                else               atomicAdd(&ev[4 * eb[j] + 3],  (nu - ur[j]));
                ur[j] = nu;
            }
        }
        __syncthreads();
        // Phase R: rebuild y = x + uc[i-1] - uc[i] + sum(ev slots)
#pragma unroll
        for (int j = 0; j < EPT; ++j) {
            int i = t + j * TPB;
            bool a = (j < 2) || (i < n);
            if (a) {
                float4 e4 = *(const float4*)&ev[4 * i];
                float v = xr[j] + ((e4.x + e4.y) + (e4.z + e4.w));
                if (i > 0)     v += uc[i - 1];
                if (i < n - 1) v -= ucv[j];
                yv[j] = v;
                ys[i] = v;
            }
        }
        __syncthreads();
    }

    // ---- sparsemax via Michelot (exact, no sort) ----
    {
        float s = 0.0f;
#pragma unroll
        for (int j = 0; j < EPT; ++j) {
            int i = t + j * TPB;
            if ((j < 2) || (i < n)) s += yv[j];
        }
#pragma unroll
        for (int d = 16; d; d >>= 1) s += __shfl_xor_sync(0xffffffffu, s, d);
        if (lane == 0) red_s[wid] = s;
        __syncthreads();
        if (t == 0) {
            float ss = 0.0f;
#pragma unroll
            for (int w = 0; w < NWARP; ++w) ss += red_s[w];
            s_tau = (ss - 1.0f) / (float)n;
            s_cnt = n;
        }
        __syncthreads();
    }

    float tau = s_tau;
    int prev_cnt = s_cnt;

    for (int itm = 0; itm < 64; ++itm) {
        float s = 0.0f;
        int   c = 0;
#pragma unroll
        for (int j = 0; j < EPT; ++j) {
            int i = t + j * TPB;
            bool a = (j < 2) || (i < n);
            if (a && yv[j] > tau) { s += yv[j]; ++c; }
        }
#pragma unroll
        for (int d = 16; d; d >>= 1) {
            s += __shfl_xor_sync(0xffffffffu, s, d);
            c += __shfl_xor_sync(0xffffffffu, c, d);
        }
        if (lane == 0) { red_s[wid] = s; red_c[wid] = c; }
        __syncthreads();
        if (t == 0) {
            float ss = 0.0f; int cc = 0;
#pragma unroll
            for (int w = 0; w < NWARP; ++w) { ss += red_s[w]; cc += red_c[w]; }
            s_tau = (ss - 1.0f) / (float)cc;
            s_cnt = cc;
        }
        __syncthreads();
        tau = s_tau;
        int cnt_now = s_cnt;
        if (cnt_now == prev_cnt) break;
        prev_cnt = cnt_now;
    }

    float scale = (float)n;
#pragma unroll
    for (int j = 0; j < EPT; ++j) {
        int i = t + j * TPB;
        if ((j < 2) || (i < n))
            out[off + i] = fmaxf(yv[j] - tau, 0.0f) * scale;
    }
}

// ---------------------------------------------------------------------------
extern "C" void kernel_launch(void* const* d_in, const int* in_sizes, int n_in,
                              void* d_out, int out_size) {
    const float* x     = (const float*)d_in[0];
    const int*   sizes = (const int*)  d_in[1];
    const int*   edges = (const int*)  d_in[2];
    float*       out   = (float*)d_out;
    int N = in_sizes[0];
    int B = in_sizes[1];

    pre_kernel<<<B, 512>>>(sizes, edges, N, B);
    main_kernel<<<B, TPB>>>(x, sizes, edges, out, N, B);
}

// round 14
// speedup vs baseline: 1.0625x; 1.0625x over previous
#include <cuda_runtime.h>

#define NMAX  1536
#define TPB   256
#define EPT   6          // strided elements per thread (NMAX / TPB)
#define NWARP 8
#define NITER 20

__device__ int g_maxdeg;

// ---------------------------------------------------------------------------
// Kernel 1 (pre): per-group offset (redundant prefix sum) + degree count
// -> global max degree via atomicMax.
// ---------------------------------------------------------------------------
__global__ void __launch_bounds__(512)
pre_kernel(const int* __restrict__ sizes,
           const int* __restrict__ edges,
           int N, int B) {
    __shared__ int cnt[NMAX];
    __shared__ int red[16];
    __shared__ int s_off;

    int g = blockIdx.x;
    int t = threadIdx.x;
    int lane = t & 31, wid = t >> 5;

    int part = 0;
    for (int i = t; i < g; i += 512) part += sizes[i];
#pragma unroll
    for (int d = 16; d; d >>= 1) part += __shfl_xor_sync(0xffffffffu, part, d);
    if (lane == 0) red[wid] = part;
    __syncthreads();
    if (t == 0) {
        int s = 0;
#pragma unroll
        for (int w = 0; w < 16; ++w) s += red[w];
        s_off = s;
    }
    int n = sizes[g];
    __syncthreads();
    int off = s_off;

    for (int i = t; i < n; i += 512)
        cnt[i] = (i == 0 || i == n - 1) ? 1 : 2;
    __syncthreads();

    const int2* e2 = (const int2*)edges;
    int reBase = (N - B) + off;
    for (int i = t; i < n; i += 512) {
        int2 e = e2[reBase + i];
        atomicAdd(&cnt[e.x - off], 1);
        atomicAdd(&cnt[e.y - off], 1);
    }
    __syncthreads();

    int m = 0;
    for (int i = t; i < n; i += 512) m = max(m, cnt[i]);
#pragma unroll
    for (int d = 16; d; d >>= 1) m = max(m, __shfl_xor_sync(0xffffffffu, m, d));
    if (lane == 0) red[wid] = m;
    __syncthreads();
    if (t == 0) {
        int mm = red[0];
#pragma unroll
        for (int w = 1; w < 16; ++w) mm = max(mm, red[w]);
        atomicMax(&g_maxdeg, mm);
    }
}

// ---------------------------------------------------------------------------
// Kernel 2 (main): fused per-group solve. R8 structure with SoA ev layout:
// ev[slot*NMAX + node] — scatter stores spread across all 32 banks.
// Overflow (rand-deg>4) via rare delta-atomics into ovf[] with skip flag.
// ---------------------------------------------------------------------------
__global__ void __launch_bounds__(TPB, 3)
main_kernel(const float* __restrict__ x,
            const int*   __restrict__ sizes,
            const int*   __restrict__ edges,
            float*       __restrict__ out,
            int N, int B) {
    __shared__ float ys[NMAX];
    __shared__ float uc[NMAX];
    __shared__ float ev[4 * NMAX];     // SoA: slot s of node i at ev[s*NMAX + i]
    __shared__ float ovf[NMAX];        // overflow accum; int-aliased as cnt during setup
    __shared__ float red_s[NWARP];
    __shared__ int   red_c[NWARP];
    __shared__ int   red_i[NWARP];
    __shared__ float s_tau;
    __shared__ int   s_cnt;
    __shared__ int   s_off;

    int g = blockIdx.x;
    int t = threadIdx.x;
    int lane = t & 31, wid = t >> 5;

    // offset[g] = sum of sizes[0..g)  (redundant recompute; L2-resident)
    {
        int part = 0;
        for (int i = t; i < g; i += TPB) part += sizes[i];
#pragma unroll
        for (int d = 16; d; d >>= 1) part += __shfl_xor_sync(0xffffffffu, part, d);
        if (lane == 0) red_i[wid] = part;
        __syncthreads();
        if (t == 0) {
            int s = 0;
#pragma unroll
            for (int w = 0; w < NWARP; ++w) s += red_i[w];
            s_off = s;
        }
    }
    int n = sizes[g];
    __syncthreads();
    int off = s_off;
    int reBase = (N - B) + off;

    float xr[EPT], ur[EPT], ucv[EPT], yv[EPT];
    int   ea[EPT], eb[EPT];
    unsigned slp[EPT];     // packed slot addrs: sa | (sb<<16); 0xFFFF = overflow
    bool  hasovf[EPT];

    int* cnt = (int*)ovf;

    const int2* e2 = (const int2*)edges;
#pragma unroll
    for (int j = 0; j < EPT; ++j) {
        int i = t + j * TPB;
        bool a = (j < 2) || (i < n);   // first 512 slots always active (n>=512)
        if (a) {
            xr[j] = x[off + i];
            int2 e = e2[reBase + i];
            ea[j] = e.x - off;
            eb[j] = e.y - off;
            ys[i] = xr[j];
        } else {
            xr[j] = 0.0f; ea[j] = 0; eb[j] = 0;
            ys[i] = 0.0f;
        }
        uc[i] = 0.0f; cnt[i] = 0;
        yv[j]  = xr[j];
        ur[j]  = 0.0f;
        ucv[j] = 0.0f;
    }
#pragma unroll
    for (int k = 0; k < 4 * EPT; ++k)
        ev[t + k * TPB] = 0.0f;
    float step = 0.5f / (float)g_maxdeg;
    __syncthreads();

    // claim per-endpoint slots; precompute packed SoA store addresses
#pragma unroll
    for (int j = 0; j < EPT; ++j) {
        int i = t + j * TPB;
        bool a = (j < 2) || (i < n);
        if (a) {
            int pa = atomicAdd(&cnt[ea[j]], 1);
            int pb = atomicAdd(&cnt[eb[j]], 1);
            unsigned sa = (pa < 4) ? (unsigned)(ea[j] + pa * NMAX) : 0xFFFFu;
            unsigned sb = (pb < 4) ? (unsigned)(eb[j] + pb * NMAX) : 0xFFFFu;
            slp[j] = sa | (sb << 16);
        } else slp[j] = 0xFFFFu | (0xFFFFu << 16);
    }
    __syncthreads();
    // read overflow flags, then re-init ovf as float zero
#pragma unroll
    for (int j = 0; j < EPT; ++j) {
        int i = t + j * TPB;
        hasovf[j] = (cnt[i] > 4);
    }
    __syncthreads();
#pragma unroll
    for (int j = 0; j < EPT; ++j) {
        int i = t + j * TPB;
        ovf[i] = 0.0f;
    }
    __syncthreads();

    // ---- 20 iterations, 2 barriers each ----
    for (int it = 0; it < NITER; ++it) {
        // Phase P: dual updates from current y; publish contributions.
#pragma unroll
        for (int j = 0; j < EPT; ++j) {
            int i = t + j * TPB;
            bool a = (j < 2) || (i < n);
            if (a) {
                if (i < n - 1) {
                    float nu = ucv[j] + step * (yv[j] - ys[i + 1]);
                    nu = fminf(1.0f, fmaxf(-1.0f, nu));
                    ucv[j] = nu;
                    uc[i] = nu;
                }
                float ya = ys[ea[j]], yb = ys[eb[j]];
                float nu = ur[j] + step * (ya - yb);
                nu = fminf(1.0f, fmaxf(-1.0f, nu));
                unsigned sa = slp[j] & 0xFFFFu;
                unsigned sb = slp[j] >> 16;
                if (sa != 0xFFFFu) ev[sa] = -nu;
                else               atomicAdd(&ovf[ea[j]], -(nu - ur[j]));
                if (sb != 0xFFFFu) ev[sb] =  nu;
                else               atomicAdd(&ovf[eb[j]],  (nu - ur[j]));
                ur[j] = nu;
            }
        }
        __syncthreads();
        // Phase R: rebuild y = x + uc[i-1] - uc[i] + sum(SoA slots) [+ ovf].
#pragma unroll
        for (int j = 0; j < EPT; ++j) {
            int i = t + j * TPB;
            bool a = (j < 2) || (i < n);
            if (a) {
                float e0 = ev[i];
                float e1 = ev[i + NMAX];
                float e2v = ev[i + 2 * NMAX];
                float e3 = ev[i + 3 * NMAX];
                float v = xr[j] + ((e0 + e1) + (e2v + e3));
                if (hasovf[j]) v += ovf[i];
                if (i > 0)     v += uc[i - 1];
                if (i < n - 1) v -= ucv[j];
                yv[j] = v;
                ys[i] = v;
            }
        }
        __syncthreads();
    }

    // ---- sparsemax via Michelot (exact, no sort) ----
    {
        float s = 0.0f;
#pragma unroll
        for (int j = 0; j < EPT; ++j) {
            int i = t + j * TPB;
            if ((j < 2) || (i < n)) s += yv[j];
        }
#pragma unroll
        for (int d = 16; d; d >>= 1) s += __shfl_xor_sync(0xffffffffu, s, d);
        if (lane == 0) red_s[wid] = s;
        __syncthreads();
        if (t == 0) {
            float ss = 0.0f;
#pragma unroll
            for (int w = 0; w < NWARP; ++w) ss += red_s[w];
            s_tau = (ss - 1.0f) / (float)n;
            s_cnt = n;
        }
        __syncthreads();
    }

    float tau = s_tau;
    int prev_cnt = s_cnt;

    for (int itm = 0; itm < 64; ++itm) {
        float s = 0.0f;
        int   c = 0;
#pragma unroll
        for (int j = 0; j < EPT; ++j) {
            int i = t + j * TPB;
            bool a = (j < 2) || (i < n);
            if (a && yv[j] > tau) { s += yv[j]; ++c; }
        }
#pragma unroll
        for (int d = 16; d; d >>= 1) {
            s += __shfl_xor_sync(0xffffffffu, s, d);
            c += __shfl_xor_sync(0xffffffffu, c, d);
        }
        if (lane == 0) { red_s[wid] = s; red_c[wid] = c; }
        __syncthreads();
        if (t == 0) {
            float ss = 0.0f; int cc = 0;
#pragma unroll
            for (int w = 0; w < NWARP; ++w) { ss += red_s[w]; cc += red_c[w]; }
            s_tau = (ss - 1.0f) / (float)cc;
            s_cnt = cc;
        }
        __syncthreads();
        tau = s_tau;
        int cnt_now = s_cnt;
        if (cnt_now == prev_cnt) break;
        prev_cnt = cnt_now;
    }

    float scale = (float)n;
#pragma unroll
    for (int j = 0; j < EPT; ++j) {
        int i = t + j * TPB;
        if ((j < 2) || (i < n))
            out[off + i] = fmaxf(yv[j] - tau, 0.0f) * scale;
    }
}

// ---------------------------------------------------------------------------
extern "C" void kernel_launch(void* const* d_in, const int* in_sizes, int n_in,
                              void* d_out, int out_size) {
    const float* x     = (const float*)d_in[0];
    const int*   sizes = (const int*)  d_in[1];
    const int*   edges = (const int*)  d_in[2];
    float*       out   = (float*)d_out;
    int N = in_sizes[0];
    int B = in_sizes[1];

    pre_kernel<<<B, 512>>>(sizes, edges, N, B);
    main_kernel<<<B, TPB>>>(x, sizes, edges, out, N, B);
}